// round 15
// baseline (speedup 1.0000x reference)
#include <cuda_runtime.h>
#include <cuda_bf16.h>
#include <cstddef>

// ---------------------------------------------------------------------------
// DWReg2DDecode3D: grid_sample -> upsample GEMM -> 4x(pool -> warp-specialized
// FUSED spiral gather + bf16x2-split tensor GEMM + relu) -> head dsconv.
// B=16, SP=9.  Fused kernel: 4 producer warps (gather->smem) + 4 consumer
// warps (ldsm+mma), double-buffered, named-barrier handshake.
// ---------------------------------------------------------------------------

#define B 16
#define SP 9

typedef unsigned long long ull;
typedef __nv_bfloat16 bf16;

// scratch (device globals; no allocations allowed)
__device__ float g_gs[B * 64 * 256];          // grid-sampled feats
__device__ float g_bufB[12845056];            // conv outputs   (max 16*3136*256)
__device__ float g_bufA[25690112];            // pool outputs   (max 16*12544*128)
__device__ bf16  g_pwh[172032];               // pre-split pw high planes
__device__ bf16  g_pwl[172032];               // pre-split pw low planes
__device__ float g_dwt[8064];                 // transposed dw (per stage)

// ---------------- packed f32x2 helpers -------------------------------------
__device__ __forceinline__ void fma2(ull& d, ull a, ull b) {
    asm("fma.rn.f32x2 %0, %1, %2, %0;" : "+l"(d) : "l"(a), "l"(b));
}
__device__ __forceinline__ ull pack2(float a, float b) {
    ull u;
    asm("mov.b64 %0, {%1, %2};" : "=l"(u) : "f"(a), "f"(b));
    return u;
}
__device__ __forceinline__ ull dup2(float x) {
    ull u;
    asm("mov.b64 %0, {%1, %1};" : "=l"(u) : "f"(x));
    return u;
}
__device__ __forceinline__ float2 unpk(ull u) {
    float2 r;
    asm("mov.b64 {%0, %1}, %2;" : "=f"(r.x), "=f"(r.y) : "l"(u));
    return r;
}

// ---------------- bf16 mma helpers -----------------------------------------
__device__ __forceinline__ void mma_bf16(float4& c, const unsigned* a,
                                         const unsigned* b) {
    asm("mma.sync.aligned.m16n8k16.row.col.f32.bf16.bf16.f32 "
        "{%0,%1,%2,%3}, {%4,%5,%6,%7}, {%8,%9}, {%0,%1,%2,%3};"
        : "+f"(c.x), "+f"(c.y), "+f"(c.z), "+f"(c.w)
        : "r"(a[0]), "r"(a[1]), "r"(a[2]), "r"(a[3]), "r"(b[0]), "r"(b[1]));
}
__device__ __forceinline__ void ldsm4(unsigned* r, const bf16* p) {
    unsigned a = (unsigned)__cvta_generic_to_shared(p);
    asm volatile("ldmatrix.sync.aligned.m8n8.x4.shared.b16 {%0,%1,%2,%3}, [%4];"
                 : "=r"(r[0]), "=r"(r[1]), "=r"(r[2]), "=r"(r[3]) : "r"(a));
}
__device__ __forceinline__ void ldsm4t(unsigned* r, const bf16* p) {
    unsigned a = (unsigned)__cvta_generic_to_shared(p);
    asm volatile("ldmatrix.sync.aligned.m8n8.x4.trans.shared.b16 {%0,%1,%2,%3}, [%4];"
                 : "=r"(r[0]), "=r"(r[1]), "=r"(r[2]), "=r"(r[3]) : "r"(a));
}
// split (a,b) -> packed bf16x2 hi word + lo word
__device__ __forceinline__ void split2(float a, float b, unsigned& h, unsigned& l) {
    bf16 ha = __float2bfloat16(a), hb = __float2bfloat16(b);
    bf16 la = __float2bfloat16(a - __bfloat162float(ha));
    bf16 lb = __float2bfloat16(b - __bfloat162float(hb));
    __nv_bfloat162 hh = __halves2bfloat162(ha, hb);
    __nv_bfloat162 ll = __halves2bfloat162(la, lb);
    h = *reinterpret_cast<unsigned*>(&hh);
    l = *reinterpret_cast<unsigned*>(&ll);
}

#define BAR_SYNC(id)   asm volatile("bar.sync %0, 256;"   :: "r"(id) : "memory")
#define BAR_ARRIVE(id) asm volatile("bar.arrive %0, 256;" :: "r"(id) : "memory")

// ---------------- grid sample (bilinear, align_corners, zero pad) ----------
__global__ void __launch_bounds__(256)
k_gridsample(const float* __restrict__ uv, const float* __restrict__ feat,
             float* __restrict__ gs)
{
    const int b = blockIdx.x, c = threadIdx.x;
    const float* fb = feat + ((size_t)b * 256 + c) * 16;
    for (int p = 0; p < 64; ++p) {
        float gx = (uv[((size_t)b * 64 + p) * 2 + 0] - 0.5f) * 2.f;
        float gy = (uv[((size_t)b * 64 + p) * 2 + 1] - 0.5f) * 2.f;
        gx = fminf(fmaxf(gx, -1.f), 1.f);
        gy = fminf(fmaxf(gy, -1.f), 1.f);
        float x = (gx + 1.f) * 0.5f * 3.f;
        float y = (gy + 1.f) * 0.5f * 3.f;
        float x0f = floorf(x), y0f = floorf(y);
        int x0 = (int)x0f, y0 = (int)y0f;
        int x1 = x0 + 1, y1 = y0 + 1;
        float fx = x - x0f, fy = y - y0f;
        float wa = (1.f - fx) * (1.f - fy);
        float wb = (1.f - fx) * fy;
        float wc = fx * (1.f - fy);
        float wd = fx * fy;
        float Ia = (x0 >= 0 && x0 < 4 && y0 >= 0 && y0 < 4) ? fb[y0 * 4 + x0] : 0.f;
        float Ib = (x0 >= 0 && x0 < 4 && y1 >= 0 && y1 < 4) ? fb[y1 * 4 + x0] : 0.f;
        float Ic = (x1 >= 0 && x1 < 4 && y0 >= 0 && y0 < 4) ? fb[y0 * 4 + x1] : 0.f;
        float Id = (x1 >= 0 && x1 < 4 && y1 >= 0 && y1 < 4) ? fb[y1 * 4 + x1] : 0.f;
        gs[((size_t)b * 64 + p) * 256 + c] = Ia * wa + Ib * wb + Ic * wc + Id * wd;
    }
}

// ---------------- upsample GEMM (f32x2 packed): out[b,v,c] -----------------
__global__ void __launch_bounds__(256)
k_upsample(const float* __restrict__ up, const float* __restrict__ gs,
           float* __restrict__ out)
{
    constexpr int VT = 16;
    __shared__ ull up_p[VT / 2][64];     // packed v-pairs
    const int b = blockIdx.y, v0 = blockIdx.x * VT, c = threadIdx.x;
    for (int t = threadIdx.x; t < (VT / 2) * 64; t += 256) {
        const int i = t / 64, p = t % 64;
        up_p[i][p] = pack2(up[(size_t)(v0 + 2 * i) * 64 + p],
                           up[(size_t)(v0 + 2 * i + 1) * 64 + p]);
    }
    __syncthreads();
    ull acc[VT / 2];
#pragma unroll
    for (int i = 0; i < VT / 2; ++i) acc[i] = 0ull;
#pragma unroll 4
    for (int p = 0; p < 64; ++p) {
        const ull g2 = dup2(gs[((size_t)b * 64 + p) * 256 + c]);
#pragma unroll
        for (int i = 0; i < VT / 2; ++i) fma2(acc[i], up_p[i][p], g2);
    }
#pragma unroll
    for (int i = 0; i < VT / 2; ++i) {
        float2 r = unpk(acc[i]);
        out[((size_t)b * 784 + v0 + 2 * i) * 256 + c] = r.x;
        out[((size_t)b * 784 + v0 + 2 * i + 1) * 256 + c] = r.y;
    }
}

// ---------------- mesh up-pool ---------------------------------------------
template <int Ci>
__global__ void __launch_bounds__(256)
k_pool(const float4* __restrict__ x, const int* __restrict__ col,
       const float* __restrict__ val, float4* __restrict__ out,
       int Nin, int Nout)
{
    constexpr int CQ = Ci / 4;
    constexpr int VPB = 256 / CQ;
    const int b = blockIdx.y;
    const int n = blockIdx.x * VPB + threadIdx.x / CQ;
    const int cq = threadIdx.x % CQ;
    if (n >= Nout) return;
    const int c0 = col[3 * n + 0], c1 = col[3 * n + 1], c2 = col[3 * n + 2];
    const float v0 = val[3 * n + 0], v1 = val[3 * n + 1], v2 = val[3 * n + 2];
    const float4* xb = x + (size_t)b * Nin * CQ;
    float4 a = xb[(size_t)c0 * CQ + cq];
    float4 bb = xb[(size_t)c1 * CQ + cq];
    float4 cc = xb[(size_t)c2 * CQ + cq];
    float4 r;
    r.x = a.x * v0 + bb.x * v1 + cc.x * v2;
    r.y = a.y * v0 + bb.y * v1 + cc.y * v2;
    r.z = a.z * v0 + bb.z * v1 + cc.z * v2;
    r.w = a.w * v0 + bb.w * v1 + cc.w * v2;
    out[((size_t)b * Nout + n) * CQ + cq] = r;
}

// ---------------- fused pw pre-split ---------------------------------------
__global__ void __launch_bounds__(256)
k_splitw4(const float* __restrict__ w0, const float* __restrict__ w1,
          const float* __restrict__ w2, const float* __restrict__ w3,
          bf16* __restrict__ h, bf16* __restrict__ l)
{
    const int i = blockIdx.x * 256 + threadIdx.x;
    if (i >= 172032) return;
    float v;
    if (i < 65536)       v = w0[i];
    else if (i < 131072) v = w1[i - 65536];
    else if (i < 163840) v = w2[i - 131072];
    else                 v = w3[i - 163840];
    bf16 hh = __float2bfloat16(v);
    h[i] = hh;
    l[i] = __float2bfloat16(v - __bfloat162float(hh));
}

// ---------------- dw transpose: dwt[s][ci] = dw[ci][s] ---------------------
__global__ void __launch_bounds__(256)
k_dwt(const float* __restrict__ d0, const float* __restrict__ d1,
      const float* __restrict__ d2, const float* __restrict__ d3,
      float* __restrict__ out)
{
    const int i = blockIdx.x * 256 + threadIdx.x;
    if (i >= 8064) return;
    if (i < 2304)       { int j = i;        out[i] = d0[(j % 256) * SP + j / 256]; }
    else if (i < 4608)  { int j = i - 2304; out[i] = d1[(j % 256) * SP + j / 256]; }
    else if (i < 6912)  { int j = i - 4608; out[i] = d2[(j % 256) * SP + j / 256]; }
    else                { int j = i - 6912; out[i] = d3[(j % 128) * SP + j / 128]; }
}

// ---------------- warp-specialized FUSED gather + bf16 GEMM ----------------
// C[M,Co] = relu( (gather_dw(x))[M,K] @ pw[K,Co] ), M = B*N flat rows.
// 256 thr: warps 4-7 produce (gather+split A, copy B) into double-buffered
// smem; warps 0-3 consume (ldsm + mma, each owns Co/4 columns, both m-halves).
// Named barriers: FULL{buf}=1+buf, FREE{buf}=3+buf (128 arrive + 128 sync).
template <int K, int Co>
__global__ void __launch_bounds__(256, 2)
k_fused_ws(const float* __restrict__ x, const int* __restrict__ idx,
           const float* __restrict__ dwt, const bf16* __restrict__ Bh,
           const bf16* __restrict__ Bl, float* __restrict__ C, int N)
{
    constexpr int KK = 32;
    constexpr int NC = K / KK;
    constexpr int AST = KK + 8;              // 40
    constexpr int BST = Co + 8;
    constexpr int CW = Co / 4;               // cols per consumer warp
    constexpr int P = CW / 16;
    constexpr int NTW = CW / 8;
    constexpr int BCNT = KK * Co / 8;        // uint4 in B tile
    constexpr int BITP = BCNT / 128;         // per producer thread
    constexpr int SZ_A = 32 * AST * 2;       // bytes, one plane
    constexpr int SZ_B = KK * BST * 2;
    constexpr int SS = 2 * SZ_A + 2 * SZ_B;  // one buffer

    extern __shared__ __align__(16) char smx[];
    int* idx_s = reinterpret_cast<int*>(smx + 2 * SS);

    const int tid = threadIdx.x;
    const int lane = tid & 31;
    const int w = tid >> 5;
    const int m0 = blockIdx.x * 32;

    // stage spiral indices as flat global rows (all threads)
    for (int t = tid; t < 32 * SP; t += 256) {
        const int mloc = t / SP, s = t - mloc * SP;
        const int g = m0 + mloc;
        const int b = g / N;
        const int n = g - b * N;
        idx_s[t] = b * N + idx[(size_t)n * SP + s];
    }
    __syncthreads();

    if (w >= 4) {
        // ------------------ producer ------------------
        const int pt = tid - 128;
        const int gm = pt >> 2;              // 0..31 rows
        const int gq = pt & 3;               // quads gq and gq+4
        const int* iv = idx_s + gm * SP;
        for (int c = 0; c < NC; ++c) {
            const int buf = c & 1;
            const int kk = c * KK;
            bf16* Ah_s = reinterpret_cast<bf16*>(smx + buf * SS);
            bf16* Al_s = reinterpret_cast<bf16*>(smx + buf * SS + SZ_A);
            bf16* Bh_s = reinterpret_cast<bf16*>(smx + buf * SS + 2 * SZ_A);
            bf16* Bl_s = reinterpret_cast<bf16*>(smx + buf * SS + 2 * SZ_A + SZ_B);

            // gather both quads (regs only; issued before FREE wait)
            const int c0 = kk + gq * 4, c1 = kk + (gq + 4) * 4;
            float4 y0 = make_float4(0.f, 0.f, 0.f, 0.f);
            float4 y1 = make_float4(0.f, 0.f, 0.f, 0.f);
#pragma unroll
            for (int s = 0; s < SP; ++s) {
                const size_t roff = (size_t)iv[s] * K;
                const float4 xv0 = __ldg(reinterpret_cast<const float4*>(x + roff + c0));
                const float4 xv1 = __ldg(reinterpret_cast<const float4*>(x + roff + c1));
                const float4 dv0 = __ldg(reinterpret_cast<const float4*>(dwt + s * K + c0));
                const float4 dv1 = __ldg(reinterpret_cast<const float4*>(dwt + s * K + c1));
                y0.x = fmaf(xv0.x, dv0.x, y0.x);
                y0.y = fmaf(xv0.y, dv0.y, y0.y);
                y0.z = fmaf(xv0.z, dv0.z, y0.z);
                y0.w = fmaf(xv0.w, dv0.w, y0.w);
                y1.x = fmaf(xv1.x, dv1.x, y1.x);
                y1.y = fmaf(xv1.y, dv1.y, y1.y);
                y1.z = fmaf(xv1.z, dv1.z, y1.z);
                y1.w = fmaf(xv1.w, dv1.w, y1.w);
            }

            if (c >= 2) BAR_SYNC(3 + buf);   // wait buffer free

            {
                unsigned h0, l0, h1, l1;
                split2(y0.x, y0.y, h0, l0);
                split2(y0.z, y0.w, h1, l1);
                *reinterpret_cast<uint2*>(&Ah_s[gm * AST + gq * 4]) = make_uint2(h0, h1);
                *reinterpret_cast<uint2*>(&Al_s[gm * AST + gq * 4]) = make_uint2(l0, l1);
                split2(y1.x, y1.y, h0, l0);
                split2(y1.z, y1.w, h1, l1);
                *reinterpret_cast<uint2*>(&Ah_s[gm * AST + (gq + 4) * 4]) = make_uint2(h0, h1);
                *reinterpret_cast<uint2*>(&Al_s[gm * AST + (gq + 4) * 4]) = make_uint2(l0, l1);
            }
            // B copy (L1-hot after first blocks)
#pragma unroll
            for (int i = 0; i < BITP; ++i) {
                const int id = pt + i * 128;
                const int r = id / (Co / 8), nq = id % (Co / 8);
                const size_t off = (size_t)(kk + r) * Co + nq * 8;
                const uint4 vh = __ldg(reinterpret_cast<const uint4*>(Bh + off));
                const uint4 vl = __ldg(reinterpret_cast<const uint4*>(Bl + off));
                *reinterpret_cast<uint4*>(&Bh_s[r * BST + nq * 8]) = vh;
                *reinterpret_cast<uint4*>(&Bl_s[r * BST + nq * 8]) = vl;
            }
            BAR_ARRIVE(1 + buf);             // signal full
        }
    } else {
        // ------------------ consumer ------------------
        const int wn = w;                    // 0..3
        const int g8 = lane >> 3, rr = lane & 7;
        const int lk = lane & 3, lr = lane >> 2;

        float4 acc[2][NTW];
#pragma unroll
        for (int mt = 0; mt < 2; ++mt)
#pragma unroll
            for (int nt = 0; nt < NTW; ++nt)
                acc[mt][nt] = make_float4(0.f, 0.f, 0.f, 0.f);

        for (int c = 0; c < NC; ++c) {
            const int buf = c & 1;
            const bf16* Ah_s = reinterpret_cast<const bf16*>(smx + buf * SS);
            const bf16* Al_s = reinterpret_cast<const bf16*>(smx + buf * SS + SZ_A);
            const bf16* Bh_s = reinterpret_cast<const bf16*>(smx + buf * SS + 2 * SZ_A);
            const bf16* Bl_s = reinterpret_cast<const bf16*>(smx + buf * SS + 2 * SZ_A + SZ_B);

            BAR_SYNC(1 + buf);               // wait full
#pragma unroll
            for (int ks = 0; ks < KK; ks += 16) {
                unsigned ah[2][4], al[2][4];
#pragma unroll
                for (int mt = 0; mt < 2; ++mt) {
                    const int row = mt * 16 + (g8 & 1) * 8 + rr;
                    const int col = ks + (g8 >> 1) * 8;
                    ldsm4(ah[mt], &Ah_s[row * AST + col]);
                    ldsm4(al[mt], &Al_s[row * AST + col]);
                }
#pragma unroll
                for (int p = 0; p < P; ++p) {
                    unsigned bh[4], bl[4];
                    const int krow = ks + (g8 & 1) * 8 + rr;
                    const int ncol = wn * CW + p * 16 + (g8 >> 1) * 8;
                    ldsm4t(bh, &Bh_s[krow * BST + ncol]);
                    ldsm4t(bl, &Bl_s[krow * BST + ncol]);
#pragma unroll
                    for (int mt = 0; mt < 2; ++mt) {
                        mma_bf16(acc[mt][2 * p], ah[mt], bh);
                        mma_bf16(acc[mt][2 * p], ah[mt], bl);
                        mma_bf16(acc[mt][2 * p], al[mt], bh);
                        mma_bf16(acc[mt][2 * p + 1], ah[mt], bh + 2);
                        mma_bf16(acc[mt][2 * p + 1], ah[mt], bl + 2);
                        mma_bf16(acc[mt][2 * p + 1], al[mt], bh + 2);
                    }
                }
            }
            BAR_ARRIVE(3 + buf);             // signal free
        }

        // epilogue: relu + store (flat rows)
#pragma unroll
        for (int mt = 0; mt < 2; ++mt) {
            const int rowl = mt * 16 + lr;
#pragma unroll
            for (int nt = 0; nt < NTW; ++nt) {
                const int colg = wn * CW + nt * 8 + 2 * lk;
                float2 o0 = make_float2(fmaxf(acc[mt][nt].x, 0.f),
                                        fmaxf(acc[mt][nt].y, 0.f));
                float2 o1 = make_float2(fmaxf(acc[mt][nt].z, 0.f),
                                        fmaxf(acc[mt][nt].w, 0.f));
                *reinterpret_cast<float2*>(
                    C + (size_t)(m0 + rowl) * Co + colg) = o0;
                *reinterpret_cast<float2*>(
                    C + (size_t)(m0 + rowl + 8) * Co + colg) = o1;
            }
        }
    }
}

// ---------------- head: Ci=64 -> Co=3, float4 gathers ----------------------
__global__ void __launch_bounds__(256)
k_head(const float* __restrict__ x, const int* __restrict__ idx,
       const float* __restrict__ dw, const float* __restrict__ pw,
       float* __restrict__ out, int N)
{
    constexpr int Ci = 64;
    constexpr int VT = 64;
    constexpr int TPV = Ci / 4;
    constexpr int VG = 256 / TPV;
    constexpr int VCH = VT / VG;
    __shared__ __align__(16) float y_s[VT][Ci + 4];
    __shared__ float pw_s[Ci * 3];
    __shared__ int idx_s[VT * SP];
    const int b = blockIdx.y, n0 = blockIdx.x * VT, tid = threadIdx.x;

    if (tid < Ci * 3) pw_s[tid] = pw[tid];
    for (int t = tid; t < VT * SP; t += 256)
        idx_s[t] = idx[(size_t)n0 * SP + t];
    __syncthreads();

    {
        const int cq = (tid % TPV) * 4;
        const int vlo = (tid / TPV) * VCH;
        ull dw01[SP], dw23[SP];
#pragma unroll
        for (int s = 0; s < SP; ++s) {
            dw01[s] = pack2(__ldg(&dw[(size_t)(cq + 0) * SP + s]),
                            __ldg(&dw[(size_t)(cq + 1) * SP + s]));
            dw23[s] = pack2(__ldg(&dw[(size_t)(cq + 2) * SP + s]),
                            __ldg(&dw[(size_t)(cq + 3) * SP + s]));
        }
        const float* xb = x + ((size_t)b * N) * Ci + cq;
#pragma unroll 2
        for (int v = vlo; v < vlo + VCH; ++v) {
            const int* iv = idx_s + v * SP;
            ull a01 = 0ull, a23 = 0ull;
#pragma unroll
            for (int s = 0; s < SP; ++s) {
                float4 xv = *reinterpret_cast<const float4*>(
                    xb + (size_t)iv[s] * Ci);
                fma2(a01, pack2(xv.x, xv.y), dw01[s]);
                fma2(a23, pack2(xv.z, xv.w), dw23[s]);
            }
            float2 r01 = unpk(a01), r23 = unpk(a23);
            *reinterpret_cast<float4*>(&y_s[v][cq]) =
                make_float4(r01.x, r01.y, r23.x, r23.y);
        }
    }
    __syncthreads();

    if (tid < VT * 3) {
        const int v = tid / 3, co = tid % 3;
        float acc = 0.f;
#pragma unroll
        for (int ci = 0; ci < Ci; ++ci)
            acc = fmaf(y_s[v][ci], pw_s[ci * 3 + co], acc);
        out[((size_t)b * N + n0 + v) * 3 + co] = acc;
    }
}

// ---------------------------------------------------------------------------
extern "C" void kernel_launch(void* const* d_in, const int* in_sizes, int n_in,
                              void* d_out, int out_size)
{
    const float* uv   = (const float*)d_in[0];
    const float* feat = (const float*)d_in[1];
    const float* up   = (const float*)d_in[2];
    const float* dw0  = (const float*)d_in[3];
    const float* pw0  = (const float*)d_in[4];
    const float* dw1  = (const float*)d_in[5];
    const float* pw1  = (const float*)d_in[6];
    const float* dw2  = (const float*)d_in[7];
    const float* pw2  = (const float*)d_in[8];
    const float* dw3  = (const float*)d_in[9];
    const float* pw3  = (const float*)d_in[10];
    const float* dwh  = (const float*)d_in[11];
    const float* pwh  = (const float*)d_in[12];

    // Resolve input ordering ambiguity via element counts.
    const float *upv0, *upv1, *upv2, *upv3;
    const int *spi0, *spi1, *spi2, *spi3, *upc0, *upc1, *upc2, *upc3;
    if (in_sizes[13] == 37632) {
        upv0 = (const float*)d_in[13]; upv1 = (const float*)d_in[14];
        upv2 = (const float*)d_in[15]; upv3 = (const float*)d_in[16];
        spi0 = (const int*)d_in[17]; spi1 = (const int*)d_in[18];
        spi2 = (const int*)d_in[19]; spi3 = (const int*)d_in[20];
        upc0 = (const int*)d_in[21]; upc1 = (const int*)d_in[22];
        upc2 = (const int*)d_in[23]; upc3 = (const int*)d_in[24];
    } else {
        spi0 = (const int*)d_in[13]; upc0 = (const int*)d_in[14]; upv0 = (const float*)d_in[15];
        spi1 = (const int*)d_in[16]; upc1 = (const int*)d_in[17]; upv1 = (const float*)d_in[18];
        spi2 = (const int*)d_in[19]; upc2 = (const int*)d_in[20]; upv2 = (const float*)d_in[21];
        spi3 = (const int*)d_in[22]; upc3 = (const int*)d_in[23]; upv3 = (const float*)d_in[24];
    }

    float *gsP, *bufA, *bufB, *dwtP;
    bf16 *pwhP, *pwlP;
    cudaGetSymbolAddress((void**)&gsP, g_gs);
    cudaGetSymbolAddress((void**)&bufA, g_bufA);
    cudaGetSymbolAddress((void**)&bufB, g_bufB);
    cudaGetSymbolAddress((void**)&pwhP, g_pwh);
    cudaGetSymbolAddress((void**)&pwlP, g_pwl);
    cudaGetSymbolAddress((void**)&dwtP, g_dwt);
    float* outp = (float*)d_out;

    // dynamic smem sizes: 2 buffers of (2*A-plane + 2*B-plane) + idx
    constexpr int S256 = 2 * (2 * 32 * 40 * 2 + 2 * 32 * (256 + 8) * 2) + 32 * SP * 4; // 78976
    constexpr int S128 = 2 * (2 * 32 * 40 * 2 + 2 * 32 * (128 + 8) * 2) + 32 * SP * 4; // 46208
    constexpr int S64  = 2 * (2 * 32 * 40 * 2 + 2 * 32 * (64 + 8) * 2) + 32 * SP * 4;  // 29824
    cudaFuncSetAttribute(k_fused_ws<256, 256>,
                         cudaFuncAttributeMaxDynamicSharedMemorySize, S256);
    cudaFuncSetAttribute(k_fused_ws<256, 128>,
                         cudaFuncAttributeMaxDynamicSharedMemorySize, S128);
    cudaFuncSetAttribute(k_fused_ws<128, 64>,
                         cudaFuncAttributeMaxDynamicSharedMemorySize, S64);

    // pw split plane offsets (elements); dwt stage offsets
    const int O0 = 0, O1 = 65536, O2 = 131072, O3 = 163840;
    const int D0 = 0, D1 = 2304, D2 = 4608, D3 = 6912;
    k_splitw4<<<672, 256>>>(pw0, pw1, pw2, pw3, pwhP, pwlP);
    k_dwt<<<32, 256>>>(dw0, dw1, dw2, dw3, dwtP);

    // 1) grid sample; 2) upsample -> bufB (b,784,256)
    k_gridsample<<<B, 256>>>(uv, feat, gsP);
    k_upsample<<<dim3(49, B), 256>>>(up, gsP, bufB);

    // stage 0: pool 784->1568, ws-fused gather(idx_3,dw0) + GEMM 256->256
    k_pool<256><<<dim3(1568 / 4, B), 256>>>((const float4*)bufB, upc3, upv3,
                                            (float4*)bufA, 784, 1568);
    k_fused_ws<256, 256><<<B * 1568 / 32, 256, S256>>>(
        bufA, spi3, dwtP + D0, pwhP + O0, pwlP + O0, bufB, 1568);

    // stage 1: pool 1568->3136, ws-fused gather(idx_2,dw1) + GEMM 256->256
    k_pool<256><<<dim3(3136 / 4, B), 256>>>((const float4*)bufB, upc2, upv2,
                                            (float4*)bufA, 1568, 3136);
    k_fused_ws<256, 256><<<B * 3136 / 32, 256, S256>>>(
        bufA, spi2, dwtP + D1, pwhP + O1, pwlP + O1, bufB, 3136);

    // stage 2: pool 3136->6272, ws-fused gather(idx_1,dw2) + GEMM 256->128
    k_pool<256><<<dim3(6272 / 4, B), 256>>>((const float4*)bufB, upc1, upv1,
                                            (float4*)bufA, 3136, 6272);
    k_fused_ws<256, 128><<<B * 6272 / 32, 256, S128>>>(
        bufA, spi1, dwtP + D2, pwhP + O2, pwlP + O2, bufB, 6272);

    // stage 3: pool 6272->12544 (Ci=128), ws-fused gather(idx_0,dw3) + 128->64
    k_pool<128><<<dim3(12544 / 8, B), 256>>>((const float4*)bufB, upc0, upv0,
                                             (float4*)bufA, 6272, 12544);
    k_fused_ws<128, 64><<<B * 12544 / 32, 256, S64>>>(
        bufA, spi0, dwtP + D3, pwhP + O3, pwlP + O3, bufB, 12544);

    // head: Ci=64 -> 3, no relu
    k_head<<<dim3(12544 / 64, B), 256>>>(bufB, spi0, dwh, pwh, outp, 12544);
}

// round 16
// speedup vs baseline: 1.0737x; 1.0737x over previous
#include <cuda_runtime.h>
#include <cuda_bf16.h>
#include <cstddef>

// ---------------------------------------------------------------------------
// DWReg2DDecode3D: grid_sample -> upsample GEMM -> 4x(pool -> FUSED spiral
// gather + bf16x2-split tensor GEMM + relu) -> head dsconv.  B=16, SP=9.
// Fused kernel: TM=32, 256 thr, 2 blocks/SM (3 on stage3).
// ---------------------------------------------------------------------------

#define B 16
#define SP 9

typedef unsigned long long ull;
typedef __nv_bfloat16 bf16;

// scratch (device globals; no allocations allowed)
__device__ float g_gs[B * 64 * 256];          // grid-sampled feats
__device__ float g_bufB[12845056];            // conv outputs   (max 16*3136*256)
__device__ float g_bufA[25690112];            // pool outputs   (max 16*12544*128)
__device__ bf16  g_pwh[172032];               // pre-split pw high planes
__device__ bf16  g_pwl[172032];               // pre-split pw low planes
__device__ float g_dwt[8064];                 // transposed dw (per stage)

// ---------------- packed f32x2 helpers -------------------------------------
__device__ __forceinline__ void fma2(ull& d, ull a, ull b) {
    asm("fma.rn.f32x2 %0, %1, %2, %0;" : "+l"(d) : "l"(a), "l"(b));
}
__device__ __forceinline__ ull pack2(float a, float b) {
    ull u;
    asm("mov.b64 %0, {%1, %2};" : "=l"(u) : "f"(a), "f"(b));
    return u;
}
__device__ __forceinline__ ull dup2(float x) {
    ull u;
    asm("mov.b64 %0, {%1, %1};" : "=l"(u) : "f"(x));
    return u;
}
__device__ __forceinline__ float2 unpk(ull u) {
    float2 r;
    asm("mov.b64 {%0, %1}, %2;" : "=f"(r.x), "=f"(r.y) : "l"(u));
    return r;
}

// ---------------- bf16 mma helpers -----------------------------------------
__device__ __forceinline__ void mma_bf16(float4& c, const unsigned* a,
                                         const unsigned* b) {
    asm("mma.sync.aligned.m16n8k16.row.col.f32.bf16.bf16.f32 "
        "{%0,%1,%2,%3}, {%4,%5,%6,%7}, {%8,%9}, {%0,%1,%2,%3};"
        : "+f"(c.x), "+f"(c.y), "+f"(c.z), "+f"(c.w)
        : "r"(a[0]), "r"(a[1]), "r"(a[2]), "r"(a[3]), "r"(b[0]), "r"(b[1]));
}
__device__ __forceinline__ void ldsm4(unsigned* r, const bf16* p) {
    unsigned a = (unsigned)__cvta_generic_to_shared(p);
    asm volatile("ldmatrix.sync.aligned.m8n8.x4.shared.b16 {%0,%1,%2,%3}, [%4];"
                 : "=r"(r[0]), "=r"(r[1]), "=r"(r[2]), "=r"(r[3]) : "r"(a));
}
__device__ __forceinline__ void ldsm4t(unsigned* r, const bf16* p) {
    unsigned a = (unsigned)__cvta_generic_to_shared(p);
    asm volatile("ldmatrix.sync.aligned.m8n8.x4.trans.shared.b16 {%0,%1,%2,%3}, [%4];"
                 : "=r"(r[0]), "=r"(r[1]), "=r"(r[2]), "=r"(r[3]) : "r"(a));
}
// split (a,b) -> packed bf16x2 hi word + lo word
__device__ __forceinline__ void split2(float a, float b, unsigned& h, unsigned& l) {
    bf16 ha = __float2bfloat16(a), hb = __float2bfloat16(b);
    bf16 la = __float2bfloat16(a - __bfloat162float(ha));
    bf16 lb = __float2bfloat16(b - __bfloat162float(hb));
    __nv_bfloat162 hh = __halves2bfloat162(ha, hb);
    __nv_bfloat162 ll = __halves2bfloat162(la, lb);
    h = *reinterpret_cast<unsigned*>(&hh);
    l = *reinterpret_cast<unsigned*>(&ll);
}

// ---------------- grid sample (bilinear, align_corners, zero pad) ----------
__global__ void __launch_bounds__(256)
k_gridsample(const float* __restrict__ uv, const float* __restrict__ feat,
             float* __restrict__ gs)
{
    const int b = blockIdx.x, c = threadIdx.x;
    const float* fb = feat + ((size_t)b * 256 + c) * 16;
    for (int p = 0; p < 64; ++p) {
        float gx = (uv[((size_t)b * 64 + p) * 2 + 0] - 0.5f) * 2.f;
        float gy = (uv[((size_t)b * 64 + p) * 2 + 1] - 0.5f) * 2.f;
        gx = fminf(fmaxf(gx, -1.f), 1.f);
        gy = fminf(fmaxf(gy, -1.f), 1.f);
        float x = (gx + 1.f) * 0.5f * 3.f;
        float y = (gy + 1.f) * 0.5f * 3.f;
        float x0f = floorf(x), y0f = floorf(y);
        int x0 = (int)x0f, y0 = (int)y0f;
        int x1 = x0 + 1, y1 = y0 + 1;
        float fx = x - x0f, fy = y - y0f;
        float wa = (1.f - fx) * (1.f - fy);
        float wb = (1.f - fx) * fy;
        float wc = fx * (1.f - fy);
        float wd = fx * fy;
        float Ia = (x0 >= 0 && x0 < 4 && y0 >= 0 && y0 < 4) ? fb[y0 * 4 + x0] : 0.f;
        float Ib = (x0 >= 0 && x0 < 4 && y1 >= 0 && y1 < 4) ? fb[y1 * 4 + x0] : 0.f;
        float Ic = (x1 >= 0 && x1 < 4 && y0 >= 0 && y0 < 4) ? fb[y0 * 4 + x1] : 0.f;
        float Id = (x1 >= 0 && x1 < 4 && y1 >= 0 && y1 < 4) ? fb[y1 * 4 + x1] : 0.f;
        gs[((size_t)b * 64 + p) * 256 + c] = Ia * wa + Ib * wb + Ic * wc + Id * wd;
    }
}

// ---------------- upsample GEMM (f32x2 packed): out[b,v,c] -----------------
__global__ void __launch_bounds__(256)
k_upsample(const float* __restrict__ up, const float* __restrict__ gs,
           float* __restrict__ out)
{
    constexpr int VT = 16;
    __shared__ ull up_p[VT / 2][64];     // packed v-pairs
    const int b = blockIdx.y, v0 = blockIdx.x * VT, c = threadIdx.x;
    for (int t = threadIdx.x; t < (VT / 2) * 64; t += 256) {
        const int i = t / 64, p = t % 64;
        up_p[i][p] = pack2(up[(size_t)(v0 + 2 * i) * 64 + p],
                           up[(size_t)(v0 + 2 * i + 1) * 64 + p]);
    }
    __syncthreads();
    ull acc[VT / 2];
#pragma unroll
    for (int i = 0; i < VT / 2; ++i) acc[i] = 0ull;
#pragma unroll 4
    for (int p = 0; p < 64; ++p) {
        const ull g2 = dup2(gs[((size_t)b * 64 + p) * 256 + c]);
#pragma unroll
        for (int i = 0; i < VT / 2; ++i) fma2(acc[i], up_p[i][p], g2);
    }
#pragma unroll
    for (int i = 0; i < VT / 2; ++i) {
        float2 r = unpk(acc[i]);
        out[((size_t)b * 784 + v0 + 2 * i) * 256 + c] = r.x;
        out[((size_t)b * 784 + v0 + 2 * i + 1) * 256 + c] = r.y;
    }
}

// ---------------- mesh up-pool ---------------------------------------------
template <int Ci>
__global__ void __launch_bounds__(256)
k_pool(const float4* __restrict__ x, const int* __restrict__ col,
       const float* __restrict__ val, float4* __restrict__ out,
       int Nin, int Nout)
{
    constexpr int CQ = Ci / 4;
    constexpr int VPB = 256 / CQ;
    const int b = blockIdx.y;
    const int n = blockIdx.x * VPB + threadIdx.x / CQ;
    const int cq = threadIdx.x % CQ;
    if (n >= Nout) return;
    const int c0 = col[3 * n + 0], c1 = col[3 * n + 1], c2 = col[3 * n + 2];
    const float v0 = val[3 * n + 0], v1 = val[3 * n + 1], v2 = val[3 * n + 2];
    const float4* xb = x + (size_t)b * Nin * CQ;
    float4 a = xb[(size_t)c0 * CQ + cq];
    float4 bb = xb[(size_t)c1 * CQ + cq];
    float4 cc = xb[(size_t)c2 * CQ + cq];
    float4 r;
    r.x = a.x * v0 + bb.x * v1 + cc.x * v2;
    r.y = a.y * v0 + bb.y * v1 + cc.y * v2;
    r.z = a.z * v0 + bb.z * v1 + cc.z * v2;
    r.w = a.w * v0 + bb.w * v1 + cc.w * v2;
    out[((size_t)b * Nout + n) * CQ + cq] = r;
}

// ---------------- prep: pw split planes + dw transpose (one launch) --------
__global__ void __launch_bounds__(256)
k_prep(const float* __restrict__ w0, const float* __restrict__ w1,
       const float* __restrict__ w2, const float* __restrict__ w3,
       bf16* __restrict__ h, bf16* __restrict__ l,
       const float* __restrict__ d0, const float* __restrict__ d1,
       const float* __restrict__ d2, const float* __restrict__ d3,
       float* __restrict__ dwt)
{
    const int i = blockIdx.x * 256 + threadIdx.x;
    if (i < 172032) {
        float v;
        if (i < 65536)       v = w0[i];
        else if (i < 131072) v = w1[i - 65536];
        else if (i < 163840) v = w2[i - 131072];
        else                 v = w3[i - 163840];
        bf16 hh = __float2bfloat16(v);
        h[i] = hh;
        l[i] = __float2bfloat16(v - __bfloat162float(hh));
    }
    if (i < 8064) {
        if (i < 2304)       { int j = i;        dwt[i] = d0[(j % 256) * SP + j / 256]; }
        else if (i < 4608)  { int j = i - 2304; dwt[i] = d1[(j % 256) * SP + j / 256]; }
        else if (i < 6912)  { int j = i - 4608; dwt[i] = d2[(j % 256) * SP + j / 256]; }
        else                { int j = i - 6912; dwt[i] = d3[(j % 128) * SP + j / 128]; }
    }
}

// ---------------- FUSED gather + bf16-split tensor GEMM --------------------
// C[M,Co] = relu( (gather_dw(x))[M,K] @ pw[K,Co] ), M = B*N flat rows.
// TM=32, 256 thr = 8 warps (2M x 4N); MAXB blocks/SM.
template <int K, int Co, int MAXB>
__global__ void __launch_bounds__(256, MAXB)
k_fused(const float* __restrict__ x, const int* __restrict__ idx,
        const float* __restrict__ dwt, const bf16* __restrict__ Bh,
        const bf16* __restrict__ Bl, float* __restrict__ C, int N)
{
    constexpr int KK = 32;
    constexpr int NC = K / KK;
    constexpr int AST = KK + 8;          // 40
    constexpr int BST = Co + 8;
    constexpr int CW = Co / 4;           // cols per warp
    constexpr int P = CW / 16;           // 16-col ldsm groups per warp
    constexpr int NTW = CW / 8;
    constexpr int BCNT = KK * Co / 8;    // uint4 elements in B tile
    constexpr int BIT = (BCNT + 255) / 256;

    __shared__ bf16 Ah_s[32 * AST], Al_s[32 * AST];
    __shared__ bf16 Bh_s[KK * BST], Bl_s[KK * BST];
    __shared__ int idx_s[32 * SP];

    const int tid = threadIdx.x;
    const int lane = tid & 31;
    const int w = tid >> 5;
    const int wm = w >> 2;               // 0..1
    const int wn = w & 3;                // 0..3
    const int m0 = blockIdx.x * 32;

    // stage spiral indices as flat global rows (b*N + idx[n][s])
    for (int t = tid; t < 32 * SP; t += 256) {
        const int mloc = t / SP, s = t - mloc * SP;
        const int g = m0 + mloc;
        const int b = g / N;
        const int n = g - b * N;
        idx_s[t] = b * N + idx[(size_t)n * SP + s];
    }
    __syncthreads();

    // gather thread map: 32 rows x 8 ci-quads
    const int gm = tid >> 3;
    const int gq = tid & 7;
    const int* iv = idx_s + gm * SP;

    float4 acc[NTW];
#pragma unroll
    for (int nt = 0; nt < NTW; ++nt)
        acc[nt] = make_float4(0.f, 0.f, 0.f, 0.f);

    const int g8 = lane >> 3, rr = lane & 7;
    const int lk = lane & 3, lr = lane >> 2;

    for (int c = 0; c < NC; ++c) {
        const int kk = c * KK;
        // ---- gather A chunk (9 taps * dwt), fp32 accumulate ----
        float4 y = make_float4(0.f, 0.f, 0.f, 0.f);
        {
            const int co0 = kk + gq * 4;
#pragma unroll
            for (int s = 0; s < SP; ++s) {
                const float4 xv = __ldg(reinterpret_cast<const float4*>(
                    x + (size_t)iv[s] * K + co0));
                const float4 dv = __ldg(reinterpret_cast<const float4*>(
                    dwt + s * K + co0));
                y.x = fmaf(xv.x, dv.x, y.x);
                y.y = fmaf(xv.y, dv.y, y.y);
                y.z = fmaf(xv.z, dv.z, y.z);
                y.w = fmaf(xv.w, dv.w, y.w);
            }
        }
        // ---- prefetch B chunk into regs ----
        uint4 brh[BIT], brl[BIT];
#pragma unroll
        for (int i = 0; i < BIT; ++i) {
            const int id = tid + i * 256;
            if (id < BCNT) {
                const int r = id / (Co / 8), nq = id % (Co / 8);
                const size_t off = (size_t)(kk + r) * Co + nq * 8;
                brh[i] = __ldg(reinterpret_cast<const uint4*>(Bh + off));
                brl[i] = __ldg(reinterpret_cast<const uint4*>(Bl + off));
            }
        }

        __syncthreads();   // prev chunk's ldsm complete

        // ---- store A (split) + B to smem ----
        {
            unsigned h0, l0, h1, l1;
            split2(y.x, y.y, h0, l0);
            split2(y.z, y.w, h1, l1);
            *reinterpret_cast<uint2*>(&Ah_s[gm * AST + gq * 4]) =
                make_uint2(h0, h1);
            *reinterpret_cast<uint2*>(&Al_s[gm * AST + gq * 4]) =
                make_uint2(l0, l1);
        }
#pragma unroll
        for (int i = 0; i < BIT; ++i) {
            const int id = tid + i * 256;
            if (id < BCNT) {
                const int r = id / (Co / 8), nq = id % (Co / 8);
                *reinterpret_cast<uint4*>(&Bh_s[r * BST + nq * 8]) = brh[i];
                *reinterpret_cast<uint4*>(&Bl_s[r * BST + nq * 8]) = brl[i];
            }
        }
        __syncthreads();

        // ---- MMA on chunk ----
#pragma unroll
        for (int ks = 0; ks < KK; ks += 16) {
            unsigned ah[4], al[4];
            {
                const int row = wm * 16 + (g8 & 1) * 8 + rr;
                const int col = ks + (g8 >> 1) * 8;
                ldsm4(ah, &Ah_s[row * AST + col]);
                ldsm4(al, &Al_s[row * AST + col]);
            }
#pragma unroll
            for (int p = 0; p < P; ++p) {
                unsigned bh[4], bl[4];
                const int krow = ks + (g8 & 1) * 8 + rr;
                const int ncol = wn * CW + p * 16 + (g8 >> 1) * 8;
                ldsm4t(bh, &Bh_s[krow * BST + ncol]);
                ldsm4t(bl, &Bl_s[krow * BST + ncol]);
                mma_bf16(acc[2 * p], ah, bh);
                mma_bf16(acc[2 * p], ah, bl);
                mma_bf16(acc[2 * p], al, bh);
                mma_bf16(acc[2 * p + 1], ah, bh + 2);
                mma_bf16(acc[2 * p + 1], ah, bl + 2);
                mma_bf16(acc[2 * p + 1], al, bh + 2);
            }
        }
    }

    // ---- epilogue: relu + store (flat rows) ----
    {
        const int rowl = wm * 16 + lr;
#pragma unroll
        for (int nt = 0; nt < NTW; ++nt) {
            const int colg = wn * CW + nt * 8 + 2 * lk;
            float2 o0 = make_float2(fmaxf(acc[nt].x, 0.f),
                                    fmaxf(acc[nt].y, 0.f));
            float2 o1 = make_float2(fmaxf(acc[nt].z, 0.f),
                                    fmaxf(acc[nt].w, 0.f));
            *reinterpret_cast<float2*>(
                C + (size_t)(m0 + rowl) * Co + colg) = o0;
            *reinterpret_cast<float2*>(
                C + (size_t)(m0 + rowl + 8) * Co + colg) = o1;
        }
    }
}

// ---------------- head: Ci=64 -> Co=3, float4 gathers ----------------------
__global__ void __launch_bounds__(256)
k_head(const float* __restrict__ x, const int* __restrict__ idx,
       const float* __restrict__ dw, const float* __restrict__ pw,
       float* __restrict__ out, int N)
{
    constexpr int Ci = 64;
    constexpr int VT = 64;
    constexpr int TPV = Ci / 4;
    constexpr int VG = 256 / TPV;
    constexpr int VCH = VT / VG;
    __shared__ __align__(16) float y_s[VT][Ci + 4];
    __shared__ float pw_s[Ci * 3];
    __shared__ int idx_s[VT * SP];
    const int b = blockIdx.y, n0 = blockIdx.x * VT, tid = threadIdx.x;

    if (tid < Ci * 3) pw_s[tid] = pw[tid];
    for (int t = tid; t < VT * SP; t += 256)
        idx_s[t] = idx[(size_t)n0 * SP + t];
    __syncthreads();

    {
        const int cq = (tid % TPV) * 4;
        const int vlo = (tid / TPV) * VCH;
        ull dw01[SP], dw23[SP];
#pragma unroll
        for (int s = 0; s < SP; ++s) {
            dw01[s] = pack2(__ldg(&dw[(size_t)(cq + 0) * SP + s]),
                            __ldg(&dw[(size_t)(cq + 1) * SP + s]));
            dw23[s] = pack2(__ldg(&dw[(size_t)(cq + 2) * SP + s]),
                            __ldg(&dw[(size_t)(cq + 3) * SP + s]));
        }
        const float* xb = x + ((size_t)b * N) * Ci + cq;
#pragma unroll 2
        for (int v = vlo; v < vlo + VCH; ++v) {
            const int* iv = idx_s + v * SP;
            ull a01 = 0ull, a23 = 0ull;
#pragma unroll
            for (int s = 0; s < SP; ++s) {
                float4 xv = *reinterpret_cast<const float4*>(
                    xb + (size_t)iv[s] * Ci);
                fma2(a01, pack2(xv.x, xv.y), dw01[s]);
                fma2(a23, pack2(xv.z, xv.w), dw23[s]);
            }
            float2 r01 = unpk(a01), r23 = unpk(a23);
            *reinterpret_cast<float4*>(&y_s[v][cq]) =
                make_float4(r01.x, r01.y, r23.x, r23.y);
        }
    }
    __syncthreads();

    if (tid < VT * 3) {
        const int v = tid / 3, co = tid % 3;
        float acc = 0.f;
#pragma unroll
        for (int ci = 0; ci < Ci; ++ci)
            acc = fmaf(y_s[v][ci], pw_s[ci * 3 + co], acc);
        out[((size_t)b * N + n0 + v) * 3 + co] = acc;
    }
}

// ---------------------------------------------------------------------------
extern "C" void kernel_launch(void* const* d_in, const int* in_sizes, int n_in,
                              void* d_out, int out_size)
{
    const float* uv   = (const float*)d_in[0];
    const float* feat = (const float*)d_in[1];
    const float* up   = (const float*)d_in[2];
    const float* dw0  = (const float*)d_in[3];
    const float* pw0  = (const float*)d_in[4];
    const float* dw1  = (const float*)d_in[5];
    const float* pw1  = (const float*)d_in[6];
    const float* dw2  = (const float*)d_in[7];
    const float* pw2  = (const float*)d_in[8];
    const float* dw3  = (const float*)d_in[9];
    const float* pw3  = (const float*)d_in[10];
    const float* dwh  = (const float*)d_in[11];
    const float* pwh  = (const float*)d_in[12];

    // Resolve input ordering ambiguity via element counts.
    const float *upv0, *upv1, *upv2, *upv3;
    const int *spi0, *spi1, *spi2, *spi3, *upc0, *upc1, *upc2, *upc3;
    if (in_sizes[13] == 37632) {
        upv0 = (const float*)d_in[13]; upv1 = (const float*)d_in[14];
        upv2 = (const float*)d_in[15]; upv3 = (const float*)d_in[16];
        spi0 = (const int*)d_in[17]; spi1 = (const int*)d_in[18];
        spi2 = (const int*)d_in[19]; spi3 = (const int*)d_in[20];
        upc0 = (const int*)d_in[21]; upc1 = (const int*)d_in[22];
        upc2 = (const int*)d_in[23]; upc3 = (const int*)d_in[24];
    } else {
        spi0 = (const int*)d_in[13]; upc0 = (const int*)d_in[14]; upv0 = (const float*)d_in[15];
        spi1 = (const int*)d_in[16]; upc1 = (const int*)d_in[17]; upv1 = (const float*)d_in[18];
        spi2 = (const int*)d_in[19]; upc2 = (const int*)d_in[20]; upv2 = (const float*)d_in[21];
        spi3 = (const int*)d_in[22]; upc3 = (const int*)d_in[23]; upv3 = (const float*)d_in[24];
    }

    float *gsP, *bufA, *bufB, *dwtP;
    bf16 *pwhP, *pwlP;
    cudaGetSymbolAddress((void**)&gsP, g_gs);
    cudaGetSymbolAddress((void**)&bufA, g_bufA);
    cudaGetSymbolAddress((void**)&bufB, g_bufB);
    cudaGetSymbolAddress((void**)&pwhP, g_pwh);
    cudaGetSymbolAddress((void**)&pwlP, g_pwl);
    cudaGetSymbolAddress((void**)&dwtP, g_dwt);
    float* outp = (float*)d_out;

    // pw split plane offsets (elements); dwt stage offsets
    const int O0 = 0, O1 = 65536, O2 = 131072, O3 = 163840;
    const int D0 = 0, D1 = 2304, D2 = 4608, D3 = 6912;
    k_prep<<<672, 256>>>(pw0, pw1, pw2, pw3, pwhP, pwlP,
                         dw0, dw1, dw2, dw3, dwtP);

    // 1) grid sample; 2) upsample -> bufB (b,784,256)
    k_gridsample<<<B, 256>>>(uv, feat, gsP);
    k_upsample<<<dim3(49, B), 256>>>(up, gsP, bufB);

    // stage 0: pool 784->1568, fused gather(idx_3,dw0) + GEMM 256->256
    k_pool<256><<<dim3(1568 / 4, B), 256>>>((const float4*)bufB, upc3, upv3,
                                            (float4*)bufA, 784, 1568);
    k_fused<256, 256, 2><<<B * 1568 / 32, 256>>>(
        bufA, spi3, dwtP + D0, pwhP + O0, pwlP + O0, bufB, 1568);

    // stage 1: pool 1568->3136, fused gather(idx_2,dw1) + GEMM 256->256
    k_pool<256><<<dim3(3136 / 4, B), 256>>>((const float4*)bufB, upc2, upv2,
                                            (float4*)bufA, 1568, 3136);
    k_fused<256, 256, 2><<<B * 3136 / 32, 256>>>(
        bufA, spi2, dwtP + D1, pwhP + O1, pwlP + O1, bufB, 3136);

    // stage 2: pool 3136->6272, fused gather(idx_1,dw2) + GEMM 256->128
    k_pool<256><<<dim3(6272 / 4, B), 256>>>((const float4*)bufB, upc1, upv1,
                                            (float4*)bufA, 3136, 6272);
    k_fused<256, 128, 2><<<B * 6272 / 32, 256>>>(
        bufA, spi1, dwtP + D2, pwhP + O2, pwlP + O2, bufB, 6272);

    // stage 3: pool 6272->12544 (Ci=128), fused gather(idx_0,dw3) + GEMM 128->64
    k_pool<128><<<dim3(12544 / 8, B), 256>>>((const float4*)bufB, upc0, upv0,
                                             (float4*)bufA, 6272, 12544);
    k_fused<128, 64, 3><<<B * 12544 / 32, 256>>>(
        bufA, spi0, dwtP + D3, pwhP + O3, pwlP + O3, bufB, 12544);

    // head: Ci=64 -> 3, no relu
    k_head<<<dim3(12544 / 64, B), 256>>>(bufB, spi0, dwh, pwh, outp, 12544);
}

// round 17
// speedup vs baseline: 1.1317x; 1.0541x over previous
#include <cuda_runtime.h>
#include <cuda_bf16.h>
#include <cstddef>

// ---------------------------------------------------------------------------
// DWReg2DDecode3D: grid_sample -> upsample GEMM -> 4x(pool -> FUSED spiral
// gather + bf16x2-split tensor GEMM + relu) -> head dsconv.  B=16, SP=9.
// Fused kernel: TM=32, 256 thr, 2 blocks/SM (3 on stage3); packed-f32x2
// gather reduce.
// ---------------------------------------------------------------------------

#define B 16
#define SP 9

typedef unsigned long long ull;
typedef __nv_bfloat16 bf16;

// scratch (device globals; no allocations allowed)
__device__ float g_gs[B * 64 * 256];          // grid-sampled feats
__device__ float g_bufB[12845056];            // conv outputs   (max 16*3136*256)
__device__ float g_bufA[25690112];            // pool outputs   (max 16*12544*128)
__device__ bf16  g_pwh[172032];               // pre-split pw high planes
__device__ bf16  g_pwl[172032];               // pre-split pw low planes
__device__ float g_dwt[8064];                 // transposed dw (per stage)

// ---------------- packed f32x2 helpers -------------------------------------
__device__ __forceinline__ void fma2(ull& d, ull a, ull b) {
    asm("fma.rn.f32x2 %0, %1, %2, %0;" : "+l"(d) : "l"(a), "l"(b));
}
__device__ __forceinline__ ull pack2(float a, float b) {
    ull u;
    asm("mov.b64 %0, {%1, %2};" : "=l"(u) : "f"(a), "f"(b));
    return u;
}
__device__ __forceinline__ ull dup2(float x) {
    ull u;
    asm("mov.b64 %0, {%1, %1};" : "=l"(u) : "f"(x));
    return u;
}
__device__ __forceinline__ float2 unpk(ull u) {
    float2 r;
    asm("mov.b64 {%0, %1}, %2;" : "=f"(r.x), "=f"(r.y) : "l"(u));
    return r;
}

// ---------------- bf16 mma helpers -----------------------------------------
__device__ __forceinline__ void mma_bf16(float4& c, const unsigned* a,
                                         const unsigned* b) {
    asm("mma.sync.aligned.m16n8k16.row.col.f32.bf16.bf16.f32 "
        "{%0,%1,%2,%3}, {%4,%5,%6,%7}, {%8,%9}, {%0,%1,%2,%3};"
        : "+f"(c.x), "+f"(c.y), "+f"(c.z), "+f"(c.w)
        : "r"(a[0]), "r"(a[1]), "r"(a[2]), "r"(a[3]), "r"(b[0]), "r"(b[1]));
}
__device__ __forceinline__ void ldsm4(unsigned* r, const bf16* p) {
    unsigned a = (unsigned)__cvta_generic_to_shared(p);
    asm volatile("ldmatrix.sync.aligned.m8n8.x4.shared.b16 {%0,%1,%2,%3}, [%4];"
                 : "=r"(r[0]), "=r"(r[1]), "=r"(r[2]), "=r"(r[3]) : "r"(a));
}
__device__ __forceinline__ void ldsm4t(unsigned* r, const bf16* p) {
    unsigned a = (unsigned)__cvta_generic_to_shared(p);
    asm volatile("ldmatrix.sync.aligned.m8n8.x4.trans.shared.b16 {%0,%1,%2,%3}, [%4];"
                 : "=r"(r[0]), "=r"(r[1]), "=r"(r[2]), "=r"(r[3]) : "r"(a));
}
// split (a,b) -> packed bf16x2 hi word + lo word
__device__ __forceinline__ void split2(float a, float b, unsigned& h, unsigned& l) {
    bf16 ha = __float2bfloat16(a), hb = __float2bfloat16(b);
    bf16 la = __float2bfloat16(a - __bfloat162float(ha));
    bf16 lb = __float2bfloat16(b - __bfloat162float(hb));
    __nv_bfloat162 hh = __halves2bfloat162(ha, hb);
    __nv_bfloat162 ll = __halves2bfloat162(la, lb);
    h = *reinterpret_cast<unsigned*>(&hh);
    l = *reinterpret_cast<unsigned*>(&ll);
}

// ---------------- grid sample (bilinear, align_corners, zero pad) ----------
__global__ void __launch_bounds__(256)
k_gridsample(const float* __restrict__ uv, const float* __restrict__ feat,
             float* __restrict__ gs)
{
    const int b = blockIdx.y, c = threadIdx.x;
    const int p0 = blockIdx.x * 16;
    const float* fb = feat + ((size_t)b * 256 + c) * 16;
    for (int p = p0; p < p0 + 16; ++p) {
        float gx = (uv[((size_t)b * 64 + p) * 2 + 0] - 0.5f) * 2.f;
        float gy = (uv[((size_t)b * 64 + p) * 2 + 1] - 0.5f) * 2.f;
        gx = fminf(fmaxf(gx, -1.f), 1.f);
        gy = fminf(fmaxf(gy, -1.f), 1.f);
        float x = (gx + 1.f) * 0.5f * 3.f;
        float y = (gy + 1.f) * 0.5f * 3.f;
        float x0f = floorf(x), y0f = floorf(y);
        int x0 = (int)x0f, y0 = (int)y0f;
        int x1 = x0 + 1, y1 = y0 + 1;
        float fx = x - x0f, fy = y - y0f;
        float wa = (1.f - fx) * (1.f - fy);
        float wb = (1.f - fx) * fy;
        float wc = fx * (1.f - fy);
        float wd = fx * fy;
        float Ia = (x0 >= 0 && x0 < 4 && y0 >= 0 && y0 < 4) ? fb[y0 * 4 + x0] : 0.f;
        float Ib = (x0 >= 0 && x0 < 4 && y1 >= 0 && y1 < 4) ? fb[y1 * 4 + x0] : 0.f;
        float Ic = (x1 >= 0 && x1 < 4 && y0 >= 0 && y0 < 4) ? fb[y0 * 4 + x1] : 0.f;
        float Id = (x1 >= 0 && x1 < 4 && y1 >= 0 && y1 < 4) ? fb[y1 * 4 + x1] : 0.f;
        gs[((size_t)b * 64 + p) * 256 + c] = Ia * wa + Ib * wb + Ic * wc + Id * wd;
    }
}

// ---------------- upsample GEMM (f32x2 packed): out[b,v,c] -----------------
__global__ void __launch_bounds__(256)
k_upsample(const float* __restrict__ up, const float* __restrict__ gs,
           float* __restrict__ out)
{
    constexpr int VT = 16;
    __shared__ ull up_p[VT / 2][64];     // packed v-pairs
    const int b = blockIdx.y, v0 = blockIdx.x * VT, c = threadIdx.x;
    for (int t = threadIdx.x; t < (VT / 2) * 64; t += 256) {
        const int i = t / 64, p = t % 64;
        up_p[i][p] = pack2(up[(size_t)(v0 + 2 * i) * 64 + p],
                           up[(size_t)(v0 + 2 * i + 1) * 64 + p]);
    }
    __syncthreads();
    ull acc[VT / 2];
#pragma unroll
    for (int i = 0; i < VT / 2; ++i) acc[i] = 0ull;
#pragma unroll 4
    for (int p = 0; p < 64; ++p) {
        const ull g2 = dup2(gs[((size_t)b * 64 + p) * 256 + c]);
#pragma unroll
        for (int i = 0; i < VT / 2; ++i) fma2(acc[i], up_p[i][p], g2);
    }
#pragma unroll
    for (int i = 0; i < VT / 2; ++i) {
        float2 r = unpk(acc[i]);
        out[((size_t)b * 784 + v0 + 2 * i) * 256 + c] = r.x;
        out[((size_t)b * 784 + v0 + 2 * i + 1) * 256 + c] = r.y;
    }
}

// ---------------- mesh up-pool ---------------------------------------------
template <int Ci>
__global__ void __launch_bounds__(256)
k_pool(const float4* __restrict__ x, const int* __restrict__ col,
       const float* __restrict__ val, float4* __restrict__ out,
       int Nin, int Nout)
{
    constexpr int CQ = Ci / 4;
    constexpr int VPB = 256 / CQ;
    const int b = blockIdx.y;
    const int n = blockIdx.x * VPB + threadIdx.x / CQ;
    const int cq = threadIdx.x % CQ;
    if (n >= Nout) return;
    const int c0 = col[3 * n + 0], c1 = col[3 * n + 1], c2 = col[3 * n + 2];
    const float v0 = val[3 * n + 0], v1 = val[3 * n + 1], v2 = val[3 * n + 2];
    const float4* xb = x + (size_t)b * Nin * CQ;
    float4 a = xb[(size_t)c0 * CQ + cq];
    float4 bb = xb[(size_t)c1 * CQ + cq];
    float4 cc = xb[(size_t)c2 * CQ + cq];
    float4 r;
    r.x = a.x * v0 + bb.x * v1 + cc.x * v2;
    r.y = a.y * v0 + bb.y * v1 + cc.y * v2;
    r.z = a.z * v0 + bb.z * v1 + cc.z * v2;
    r.w = a.w * v0 + bb.w * v1 + cc.w * v2;
    out[((size_t)b * Nout + n) * CQ + cq] = r;
}

// ---------------- prep: pw split planes + dw transpose (one launch) --------
__global__ void __launch_bounds__(256)
k_prep(const float* __restrict__ w0, const float* __restrict__ w1,
       const float* __restrict__ w2, const float* __restrict__ w3,
       bf16* __restrict__ h, bf16* __restrict__ l,
       const float* __restrict__ d0, const float* __restrict__ d1,
       const float* __restrict__ d2, const float* __restrict__ d3,
       float* __restrict__ dwt)
{
    const int i = blockIdx.x * 256 + threadIdx.x;
    if (i < 172032) {
        float v;
        if (i < 65536)       v = w0[i];
        else if (i < 131072) v = w1[i - 65536];
        else if (i < 163840) v = w2[i - 131072];
        else                 v = w3[i - 163840];
        bf16 hh = __float2bfloat16(v);
        h[i] = hh;
        l[i] = __float2bfloat16(v - __bfloat162float(hh));
    }
    if (i < 8064) {
        if (i < 2304)       { int j = i;        dwt[i] = d0[(j % 256) * SP + j / 256]; }
        else if (i < 4608)  { int j = i - 2304; dwt[i] = d1[(j % 256) * SP + j / 256]; }
        else if (i < 6912)  { int j = i - 4608; dwt[i] = d2[(j % 256) * SP + j / 256]; }
        else                { int j = i - 6912; dwt[i] = d3[(j % 128) * SP + j / 128]; }
    }
}

// ---------------- FUSED gather + bf16-split tensor GEMM --------------------
// C[M,Co] = relu( (gather_dw(x))[M,K] @ pw[K,Co] ), M = B*N flat rows.
// TM=32, 256 thr = 8 warps (2M x 4N); MAXB blocks/SM.
// Gather reduce uses packed f32x2 FMAs (half the FMA issue count).
template <int K, int Co, int MAXB>
__global__ void __launch_bounds__(256, MAXB)
k_fused(const float* __restrict__ x, const int* __restrict__ idx,
        const float* __restrict__ dwt, const bf16* __restrict__ Bh,
        const bf16* __restrict__ Bl, float* __restrict__ C, int N)
{
    constexpr int KK = 32;
    constexpr int NC = K / KK;
    constexpr int AST = KK + 8;          // 40
    constexpr int BST = Co + 8;
    constexpr int CW = Co / 4;           // cols per warp
    constexpr int P = CW / 16;           // 16-col ldsm groups per warp
    constexpr int NTW = CW / 8;
    constexpr int BCNT = KK * Co / 8;    // uint4 elements in B tile
    constexpr int BIT = (BCNT + 255) / 256;

    __shared__ bf16 Ah_s[32 * AST], Al_s[32 * AST];
    __shared__ bf16 Bh_s[KK * BST], Bl_s[KK * BST];
    __shared__ int idx_s[32 * SP];

    const int tid = threadIdx.x;
    const int lane = tid & 31;
    const int w = tid >> 5;
    const int wm = w >> 2;               // 0..1
    const int wn = w & 3;                // 0..3
    const int m0 = blockIdx.x * 32;

    // stage spiral indices as flat global rows (b*N + idx[n][s])
    for (int t = tid; t < 32 * SP; t += 256) {
        const int mloc = t / SP, s = t - mloc * SP;
        const int g = m0 + mloc;
        const int b = g / N;
        const int n = g - b * N;
        idx_s[t] = b * N + idx[(size_t)n * SP + s];
    }
    __syncthreads();

    // gather thread map: 32 rows x 8 ci-quads
    const int gm = tid >> 3;
    const int gq = tid & 7;
    const int* iv = idx_s + gm * SP;

    float4 acc[NTW];
#pragma unroll
    for (int nt = 0; nt < NTW; ++nt)
        acc[nt] = make_float4(0.f, 0.f, 0.f, 0.f);

    const int g8 = lane >> 3, rr = lane & 7;
    const int lk = lane & 3, lr = lane >> 2;

    for (int c = 0; c < NC; ++c) {
        const int kk = c * KK;
        // ---- gather A chunk (9 taps * dwt), packed f32x2 accumulate ----
        ull y01 = 0ull, y23 = 0ull;
        {
            const int co0 = kk + gq * 4;
#pragma unroll
            for (int s = 0; s < SP; ++s) {
                const float4 xv = __ldg(reinterpret_cast<const float4*>(
                    x + (size_t)iv[s] * K + co0));
                const float4 dv = __ldg(reinterpret_cast<const float4*>(
                    dwt + s * K + co0));
                fma2(y01, pack2(xv.x, xv.y), pack2(dv.x, dv.y));
                fma2(y23, pack2(xv.z, xv.w), pack2(dv.z, dv.w));
            }
        }
        // ---- prefetch B chunk into regs ----
        uint4 brh[BIT], brl[BIT];
#pragma unroll
        for (int i = 0; i < BIT; ++i) {
            const int id = tid + i * 256;
            if (id < BCNT) {
                const int r = id / (Co / 8), nq = id % (Co / 8);
                const size_t off = (size_t)(kk + r) * Co + nq * 8;
                brh[i] = __ldg(reinterpret_cast<const uint4*>(Bh + off));
                brl[i] = __ldg(reinterpret_cast<const uint4*>(Bl + off));
            }
        }

        __syncthreads();   // prev chunk's ldsm complete

        // ---- store A (split) + B to smem ----
        {
            const float2 r01 = unpk(y01), r23 = unpk(y23);
            unsigned h0, l0, h1, l1;
            split2(r01.x, r01.y, h0, l0);
            split2(r23.x, r23.y, h1, l1);
            *reinterpret_cast<uint2*>(&Ah_s[gm * AST + gq * 4]) =
                make_uint2(h0, h1);
            *reinterpret_cast<uint2*>(&Al_s[gm * AST + gq * 4]) =
                make_uint2(l0, l1);
        }
#pragma unroll
        for (int i = 0; i < BIT; ++i) {
            const int id = tid + i * 256;
            if (id < BCNT) {
                const int r = id / (Co / 8), nq = id % (Co / 8);
                *reinterpret_cast<uint4*>(&Bh_s[r * BST + nq * 8]) = brh[i];
                *reinterpret_cast<uint4*>(&Bl_s[r * BST + nq * 8]) = brl[i];
            }
        }
        __syncthreads();

        // ---- MMA on chunk ----
#pragma unroll
        for (int ks = 0; ks < KK; ks += 16) {
            unsigned ah[4], al[4];
            {
                const int row = wm * 16 + (g8 & 1) * 8 + rr;
                const int col = ks + (g8 >> 1) * 8;
                ldsm4(ah, &Ah_s[row * AST + col]);
                ldsm4(al, &Al_s[row * AST + col]);
            }
#pragma unroll
            for (int p = 0; p < P; ++p) {
                unsigned bh[4], bl[4];
                const int krow = ks + (g8 & 1) * 8 + rr;
                const int ncol = wn * CW + p * 16 + (g8 >> 1) * 8;
                ldsm4t(bh, &Bh_s[krow * BST + ncol]);
                ldsm4t(bl, &Bl_s[krow * BST + ncol]);
                mma_bf16(acc[2 * p], ah, bh);
                mma_bf16(acc[2 * p], ah, bl);
                mma_bf16(acc[2 * p], al, bh);
                mma_bf16(acc[2 * p + 1], ah, bh + 2);
                mma_bf16(acc[2 * p + 1], ah, bl + 2);
                mma_bf16(acc[2 * p + 1], al, bh + 2);
            }
        }
    }

    // ---- epilogue: relu + store (flat rows) ----
    {
        const int rowl = wm * 16 + lr;
#pragma unroll
        for (int nt = 0; nt < NTW; ++nt) {
            const int colg = wn * CW + nt * 8 + 2 * lk;
            float2 o0 = make_float2(fmaxf(acc[nt].x, 0.f),
                                    fmaxf(acc[nt].y, 0.f));
            float2 o1 = make_float2(fmaxf(acc[nt].z, 0.f),
                                    fmaxf(acc[nt].w, 0.f));
            *reinterpret_cast<float2*>(
                C + (size_t)(m0 + rowl) * Co + colg) = o0;
            *reinterpret_cast<float2*>(
                C + (size_t)(m0 + rowl + 8) * Co + colg) = o1;
        }
    }
}

// ---------------- head: Ci=64 -> Co=3, float4 gathers ----------------------
__global__ void __launch_bounds__(256)
k_head(const float* __restrict__ x, const int* __restrict__ idx,
       const float* __restrict__ dw, const float* __restrict__ pw,
       float* __restrict__ out, int N)
{
    constexpr int Ci = 64;
    constexpr int VT = 64;
    constexpr int TPV = Ci / 4;
    constexpr int VG = 256 / TPV;
    constexpr int VCH = VT / VG;
    __shared__ __align__(16) float y_s[VT][Ci + 4];
    __shared__ float pw_s[Ci * 3];
    __shared__ int idx_s[VT * SP];
    const int b = blockIdx.y, n0 = blockIdx.x * VT, tid = threadIdx.x;

    if (tid < Ci * 3) pw_s[tid] = pw[tid];
    for (int t = tid; t < VT * SP; t += 256)
        idx_s[t] = idx[(size_t)n0 * SP + t];
    __syncthreads();

    {
        const int cq = (tid % TPV) * 4;
        const int vlo = (tid / TPV) * VCH;
        ull dw01[SP], dw23[SP];
#pragma unroll
        for (int s = 0; s < SP; ++s) {
            dw01[s] = pack2(__ldg(&dw[(size_t)(cq + 0) * SP + s]),
                            __ldg(&dw[(size_t)(cq + 1) * SP + s]));
            dw23[s] = pack2(__ldg(&dw[(size_t)(cq + 2) * SP + s]),
                            __ldg(&dw[(size_t)(cq + 3) * SP + s]));
        }
        const float* xb = x + ((size_t)b * N) * Ci + cq;
#pragma unroll 2
        for (int v = vlo; v < vlo + VCH; ++v) {
            const int* iv = idx_s + v * SP;
            ull a01 = 0ull, a23 = 0ull;
#pragma unroll
            for (int s = 0; s < SP; ++s) {
                float4 xv = *reinterpret_cast<const float4*>(
                    xb + (size_t)iv[s] * Ci);
                fma2(a01, pack2(xv.x, xv.y), dw01[s]);
                fma2(a23, pack2(xv.z, xv.w), dw23[s]);
            }
            float2 r01 = unpk(a01), r23 = unpk(a23);
            *reinterpret_cast<float4*>(&y_s[v][cq]) =
                make_float4(r01.x, r01.y, r23.x, r23.y);
        }
    }
    __syncthreads();

    if (tid < VT * 3) {
        const int v = tid / 3, co = tid % 3;
        float acc = 0.f;
#pragma unroll
        for (int ci = 0; ci < Ci; ++ci)
            acc = fmaf(y_s[v][ci], pw_s[ci * 3 + co], acc);
        out[((size_t)b * N + n0 + v) * 3 + co] = acc;
    }
}

// ---------------------------------------------------------------------------
extern "C" void kernel_launch(void* const* d_in, const int* in_sizes, int n_in,
                              void* d_out, int out_size)
{
    const float* uv   = (const float*)d_in[0];
    const float* feat = (const float*)d_in[1];
    const float* up   = (const float*)d_in[2];
    const float* dw0  = (const float*)d_in[3];
    const float* pw0  = (const float*)d_in[4];
    const float* dw1  = (const float*)d_in[5];
    const float* pw1  = (const float*)d_in[6];
    const float* dw2  = (const float*)d_in[7];
    const float* pw2  = (const float*)d_in[8];
    const float* dw3  = (const float*)d_in[9];
    const float* pw3  = (const float*)d_in[10];
    const float* dwh  = (const float*)d_in[11];
    const float* pwh  = (const float*)d_in[12];

    // Resolve input ordering ambiguity via element counts.
    const float *upv0, *upv1, *upv2, *upv3;
    const int *spi0, *spi1, *spi2, *spi3, *upc0, *upc1, *upc2, *upc3;
    if (in_sizes[13] == 37632) {
        upv0 = (const float*)d_in[13]; upv1 = (const float*)d_in[14];
        upv2 = (const float*)d_in[15]; upv3 = (const float*)d_in[16];
        spi0 = (const int*)d_in[17]; spi1 = (const int*)d_in[18];
        spi2 = (const int*)d_in[19]; spi3 = (const int*)d_in[20];
        upc0 = (const int*)d_in[21]; upc1 = (const int*)d_in[22];
        upc2 = (const int*)d_in[23]; upc3 = (const int*)d_in[24];
    } else {
        spi0 = (const int*)d_in[13]; upc0 = (const int*)d_in[14]; upv0 = (const float*)d_in[15];
        spi1 = (const int*)d_in[16]; upc1 = (const int*)d_in[17]; upv1 = (const float*)d_in[18];
        spi2 = (const int*)d_in[19]; upc2 = (const int*)d_in[20]; upv2 = (const float*)d_in[21];
        spi3 = (const int*)d_in[22]; upc3 = (const int*)d_in[23]; upv3 = (const float*)d_in[24];
    }

    float *gsP, *bufA, *bufB, *dwtP;
    bf16 *pwhP, *pwlP;
    cudaGetSymbolAddress((void**)&gsP, g_gs);
    cudaGetSymbolAddress((void**)&bufA, g_bufA);
    cudaGetSymbolAddress((void**)&bufB, g_bufB);
    cudaGetSymbolAddress((void**)&pwhP, g_pwh);
    cudaGetSymbolAddress((void**)&pwlP, g_pwl);
    cudaGetSymbolAddress((void**)&dwtP, g_dwt);
    float* outp = (float*)d_out;

    // pw split plane offsets (elements); dwt stage offsets
    const int O0 = 0, O1 = 65536, O2 = 131072, O3 = 163840;
    const int D0 = 0, D1 = 2304, D2 = 4608, D3 = 6912;
    k_prep<<<672, 256>>>(pw0, pw1, pw2, pw3, pwhP, pwlP,
                         dw0, dw1, dw2, dw3, dwtP);

    // 1) grid sample; 2) upsample -> bufB (b,784,256)
    k_gridsample<<<dim3(4, B), 256>>>(uv, feat, gsP);
    k_upsample<<<dim3(49, B), 256>>>(up, gsP, bufB);

    // stage 0: pool 784->1568, fused gather(idx_3,dw0) + GEMM 256->256
    k_pool<256><<<dim3(1568 / 4, B), 256>>>((const float4*)bufB, upc3, upv3,
                                            (float4*)bufA, 784, 1568);
    k_fused<256, 256, 2><<<B * 1568 / 32, 256>>>(
        bufA, spi3, dwtP + D0, pwhP + O0, pwlP + O0, bufB, 1568);

    // stage 1: pool 1568->3136, fused gather(idx_2,dw1) + GEMM 256->256
    k_pool<256><<<dim3(3136 / 4, B), 256>>>((const float4*)bufB, upc2, upv2,
                                            (float4*)bufA, 1568, 3136);
    k_fused<256, 256, 2><<<B * 3136 / 32, 256>>>(
        bufA, spi2, dwtP + D1, pwhP + O1, pwlP + O1, bufB, 3136);

    // stage 2: pool 3136->6272, fused gather(idx_1,dw2) + GEMM 256->128
    k_pool<256><<<dim3(6272 / 4, B), 256>>>((const float4*)bufB, upc1, upv1,
                                            (float4*)bufA, 3136, 6272);
    k_fused<256, 128, 2><<<B * 6272 / 32, 256>>>(
        bufA, spi1, dwtP + D2, pwhP + O2, pwlP + O2, bufB, 6272);

    // stage 3: pool 6272->12544 (Ci=128), fused gather(idx_0,dw3) + GEMM 128->64
    k_pool<128><<<dim3(12544 / 8, B), 256>>>((const float4*)bufB, upc0, upv0,
                                             (float4*)bufA, 6272, 12544);
    k_fused<128, 64, 3><<<B * 12544 / 32, 256>>>(
        bufA, spi0, dwtP + D3, pwhP + O3, pwlP + O3, bufB, 12544);

    // head: Ci=64 -> 3, no relu
    k_head<<<dim3(12544 / 64, B), 256>>>(bufB, spi0, dwh, pwh, outp, 12544);
}